// round 3
// baseline (speedup 1.0000x reference)
#include <cuda_runtime.h>
#include <cuda_bf16.h>
#include <cstdint>

// Problem constants
#define IN_F   4096
#define OUT_F  4096
#define RANK   8
#define MTOT   8192
#define KDIM   4096
#define NDIM   4096

// Quantized operand scratch: int8 codes in [-8,7]
__device__ int8_t g_xq[(size_t)MTOT * KDIM];   // 32 MB
__device__ int8_t g_wq[(size_t)NDIM * KDIM];   // 16 MB

__device__ __forceinline__ int qclip_i(float v) {
    return __float2int_rn(fminf(7.0f, fmaxf(-8.0f, v)));
}
__device__ __forceinline__ uint32_t pack4(int a, int b, int c, int d) {
    return (uint32_t)(a & 0xFF) | ((uint32_t)(b & 0xFF) << 8) |
           ((uint32_t)(c & 0xFF) << 16) | ((uint32_t)(d & 0xFF) << 24);
}

// ---------------------------------------------------------------------------
// Kernel 1: activation quantization -> packed int8
// ---------------------------------------------------------------------------
__global__ void quant_x_kernel(const float* __restrict__ x,
                               const float* __restrict__ tscales,
                               const int*   __restrict__ step) {
    int i = blockIdx.x * blockDim.x + threadIdx.x;   // float4 index
    const int n4 = (MTOT * KDIM) / 4;
    if (i >= n4) return;
    float inv = 1.0f / tscales[*step];
    float4 v = reinterpret_cast<const float4*>(x)[i];
    int q0 = qclip_i(v.x * inv), q1 = qclip_i(v.y * inv);
    int q2 = qclip_i(v.z * inv), q3 = qclip_i(v.w * inv);
    reinterpret_cast<uint32_t*>(g_xq)[i] = pack4(q0, q1, q2, q3);
}

// ---------------------------------------------------------------------------
// Kernel 2: LoRA merge + weight quantization -> packed int8
// ---------------------------------------------------------------------------
__global__ void quant_w_kernel(const float* __restrict__ W,
                               const float* __restrict__ lA,
                               const float* __restrict__ lB,
                               const float* __restrict__ wscale) {
    int o  = blockIdx.x;
    int i4 = threadIdx.x;            // 0..1023 -> columns i4*4 .. i4*4+3
    float b[RANK];
#pragma unroll
    for (int r = 0; r < RANK; r++) b[r] = lB[o * RANK + r];
    float inv = 1.0f / wscale[o];
    float4 w = reinterpret_cast<const float4*>(W + (size_t)o * IN_F)[i4];
    float m0 = w.x, m1 = w.y, m2 = w.z, m3 = w.w;
#pragma unroll
    for (int r = 0; r < RANK; r++) {
        float4 a = reinterpret_cast<const float4*>(lA + (size_t)r * IN_F)[i4];
        m0 += b[r] * a.x; m1 += b[r] * a.y; m2 += b[r] * a.z; m3 += b[r] * a.w;
    }
    int q0 = qclip_i(m0 * inv), q1 = qclip_i(m1 * inv);
    int q2 = qclip_i(m2 * inv), q3 = qclip_i(m3 * inv);
    reinterpret_cast<uint32_t*>(g_wq)[((size_t)o * IN_F) / 4 + i4] =
        pack4(q0, q1, q2, q3);
}

// ---------------------------------------------------------------------------
// Kernel 3: int8 GEMM, 128x128x64 tiles, 2-stage cp.async, mma.sync m16n8k32.s8
// 256 threads = 8 warps in a 4(M) x 2(N) grid; warp tile 32x64.
// Same byte geometry as round-1 bf16 kernel: 64B rows, 4x16B chunks, XOR swizzle.
// ---------------------------------------------------------------------------
#define BM 128
#define BN 128
#define BK 64
#define KTILES (KDIM / BK)   // 64

__device__ __forceinline__ uint32_t swz(int row, int chunk) {
    return (uint32_t)(row * 64 + ((chunk ^ ((row >> 1) & 3)) << 4));
}

__device__ __forceinline__ void cp_async16(uint32_t saddr, const void* gaddr) {
    asm volatile("cp.async.cg.shared.global [%0], [%1], 16;\n"
                 :: "r"(saddr), "l"(gaddr));
}

__global__ __launch_bounds__(256) void gemm_kernel(
    float* __restrict__ out,
    const float* __restrict__ wscale,
    const float* __restrict__ bias,
    const float* __restrict__ tscales,
    const int*  __restrict__ step)
{
    __shared__ __align__(128) unsigned char smem[2 * (8192 + 8192)]; // 32 KB
    const int tid   = threadIdx.x;
    const int lane  = tid & 31;
    const int warp  = tid >> 5;
    const int warpM = warp & 3;      // 0..3
    const int warpN = warp >> 2;     // 0..1
    const int bm0 = blockIdx.y * BM;
    const int bn0 = blockIdx.x * BN;

    const uint32_t sbase = (uint32_t)__cvta_generic_to_shared(smem);
    const uint32_t sA = sbase;           // 2 stages x 8KB
    const uint32_t sB = sbase + 16384;   // 2 stages x 8KB

    int32_t acc[2][8][4];
#pragma unroll
    for (int mi = 0; mi < 2; mi++)
#pragma unroll
        for (int ni = 0; ni < 8; ni++)
#pragma unroll
            for (int c = 0; c < 4; c++) acc[mi][ni][c] = 0;

    // ------- tile loader: each stage = 128 rows x 64B per operand -------
    auto load_tile = [&](int s, int kt) {
        const int k0 = kt * BK;
#pragma unroll
        for (int p = 0; p < 2; p++) {
            int ci  = tid + p * 256;   // 0..511
            int row = ci >> 2;
            int c   = ci & 3;
            const int8_t* ga = &g_xq[(size_t)(bm0 + row) * KDIM + k0 + c * 16];
            cp_async16(sA + s * 8192 + swz(row, c), ga);
            const int8_t* gb = &g_wq[(size_t)(bn0 + row) * KDIM + k0 + c * 16];
            cp_async16(sB + s * 8192 + swz(row, c), gb);
        }
        asm volatile("cp.async.commit_group;\n" ::);
    };

    load_tile(0, 0);

    const int q = lane >> 3;     // ldmatrix quadrant
    const int w = lane & 7;

    for (int kt = 0; kt < KTILES; ++kt) {
        const int s = kt & 1;
        if (kt < KTILES - 1) {
            load_tile(s ^ 1, kt + 1);
            asm volatile("cp.async.wait_group 1;\n" ::);
        } else {
            asm volatile("cp.async.wait_group 0;\n" ::);
        }
        __syncthreads();

#pragma unroll
        for (int kk = 0; kk < 2; kk++) {   // each kk = 32 int8 of K (2 chunks)
            // A fragments: 2 m-tiles of 16x32 int8 (= 16x16 b16 view)
            uint32_t aF[2][4];
#pragma unroll
            for (int mi = 0; mi < 2; mi++) {
                int r  = warpM * 32 + mi * 16 + w + 8 * (q & 1);
                int ch = 2 * kk + (q >> 1);
                uint32_t addr = sA + s * 8192 + swz(r, ch);
                asm volatile(
                    "ldmatrix.sync.aligned.m8n8.x4.shared.b16 {%0,%1,%2,%3}, [%4];\n"
                    : "=r"(aF[mi][0]), "=r"(aF[mi][1]), "=r"(aF[mi][2]), "=r"(aF[mi][3])
                    : "r"(addr));
            }
            // B fragments: 8 n-tiles of 8x32 int8
            uint32_t bF[8][2];
#pragma unroll
            for (int j = 0; j < 4; j++) {
                int r  = warpN * 64 + j * 16 + w + 8 * (q & 1);
                int ch = 2 * kk + (q >> 1);
                uint32_t addr = sB + s * 8192 + swz(r, ch);
                uint32_t t0, t1, t2, t3;
                asm volatile(
                    "ldmatrix.sync.aligned.m8n8.x4.shared.b16 {%0,%1,%2,%3}, [%4];\n"
                    : "=r"(t0), "=r"(t1), "=r"(t2), "=r"(t3)
                    : "r"(addr));
                bF[2 * j][0] = t0; bF[2 * j + 1][0] = t1;
                bF[2 * j][1] = t2; bF[2 * j + 1][1] = t3;
            }
#pragma unroll
            for (int mi = 0; mi < 2; mi++)
#pragma unroll
                for (int ni = 0; ni < 8; ni++) {
                    asm volatile(
                        "mma.sync.aligned.m16n8k32.row.col.s32.s8.s8.s32 "
                        "{%0,%1,%2,%3}, {%4,%5,%6,%7}, {%8,%9}, {%0,%1,%2,%3};\n"
                        : "+r"(acc[mi][ni][0]), "+r"(acc[mi][ni][1]),
                          "+r"(acc[mi][ni][2]), "+r"(acc[mi][ni][3])
                        : "r"(aF[mi][0]), "r"(aF[mi][1]), "r"(aF[mi][2]), "r"(aF[mi][3]),
                          "r"(bF[ni][0]), "r"(bF[ni][1]));
                }
        }
        __syncthreads();
    }

    // ------- epilogue: out = acc * ts*scale[o] + bias[o] -------
    const float ts = tscales[*step];
#pragma unroll
    for (int ni = 0; ni < 8; ni++) {
        int gn = bn0 + warpN * 64 + ni * 8 + (lane & 3) * 2;
        float s0 = wscale[gn]     * ts;
        float s1 = wscale[gn + 1] * ts;
        float b0 = bias[gn];
        float b1 = bias[gn + 1];
#pragma unroll
        for (int mi = 0; mi < 2; mi++) {
            int gm = bm0 + warpM * 32 + mi * 16 + (lane >> 2);
            float2 r01;
            r01.x = (float)acc[mi][ni][0] * s0 + b0;
            r01.y = (float)acc[mi][ni][1] * s1 + b1;
            *reinterpret_cast<float2*>(&out[(size_t)gm * NDIM + gn]) = r01;
            float2 r23;
            r23.x = (float)acc[mi][ni][2] * s0 + b0;
            r23.y = (float)acc[mi][ni][3] * s1 + b1;
            *reinterpret_cast<float2*>(&out[(size_t)(gm + 8) * NDIM + gn]) = r23;
        }
    }
}

// ---------------------------------------------------------------------------
// launch: 0=x 1=W 2=lora_A 3=lora_B 4=weight_scale 5=temporal_scales 6=bias 7=step
// ---------------------------------------------------------------------------
extern "C" void kernel_launch(void* const* d_in, const int* in_sizes, int n_in,
                              void* d_out, int out_size) {
    const float* x   = (const float*)d_in[0];
    const float* W   = (const float*)d_in[1];
    const float* lA  = (const float*)d_in[2];
    const float* lB  = (const float*)d_in[3];
    const float* ws  = (const float*)d_in[4];
    const float* tsc = (const float*)d_in[5];
    const float* bia = (const float*)d_in[6];
    const int*   stp = (const int*)  d_in[7];
    float* out = (float*)d_out;

    {
        int n4 = (MTOT * KDIM) / 4;
        quant_x_kernel<<<(n4 + 255) / 256, 256>>>(x, tsc, stp);
    }
    quant_w_kernel<<<NDIM, 1024>>>(W, lA, lB, ws);
    {
        dim3 grid(NDIM / BN, MTOT / BM);   // (32, 64)
        gemm_kernel<<<grid, 256>>>(out, ws, bia, tsc, stp);
    }
}

// round 4
// speedup vs baseline: 2.2700x; 2.2700x over previous
#include <cuda_runtime.h>
#include <cuda_bf16.h>
#include <cuda_fp8.h>
#include <cstdint>

// Problem constants
#define IN_F   4096
#define OUT_F  4096
#define RANK   8
#define MTOT   8192
#define KDIM   4096
#define NDIM   4096

// Quantized operand scratch: integer codes in [-8,7] stored as e4m3 (exact)
__device__ uint8_t g_xq[(size_t)MTOT * KDIM];   // 32 MB
__device__ uint8_t g_wq[(size_t)NDIM * KDIM];   // 16 MB

__device__ __forceinline__ float qclipf(float v) {
    return fminf(7.0f, fmaxf(-8.0f, rintf(v)));
}
__device__ __forceinline__ uint32_t pack4_e4m3(float a, float b, float c, float d) {
    uint32_t r0 = __nv_cvt_float_to_fp8(a, __NV_SATFINITE, __NV_E4M3);
    uint32_t r1 = __nv_cvt_float_to_fp8(b, __NV_SATFINITE, __NV_E4M3);
    uint32_t r2 = __nv_cvt_float_to_fp8(c, __NV_SATFINITE, __NV_E4M3);
    uint32_t r3 = __nv_cvt_float_to_fp8(d, __NV_SATFINITE, __NV_E4M3);
    return r0 | (r1 << 8) | (r2 << 16) | (r3 << 24);
}

// ---------------------------------------------------------------------------
// Kernel 1: activation quantization -> packed e4m3
// ---------------------------------------------------------------------------
__global__ void quant_x_kernel(const float* __restrict__ x,
                               const float* __restrict__ tscales,
                               const int*   __restrict__ step) {
    int i = blockIdx.x * blockDim.x + threadIdx.x;   // float4 index
    const int n4 = (MTOT * KDIM) / 4;
    if (i >= n4) return;
    float inv = 1.0f / tscales[*step];
    float4 v = reinterpret_cast<const float4*>(x)[i];
    reinterpret_cast<uint32_t*>(g_xq)[i] =
        pack4_e4m3(qclipf(v.x * inv), qclipf(v.y * inv),
                   qclipf(v.z * inv), qclipf(v.w * inv));
}

// ---------------------------------------------------------------------------
// Kernel 2: LoRA merge + weight quantization -> packed e4m3
// ---------------------------------------------------------------------------
__global__ void quant_w_kernel(const float* __restrict__ W,
                               const float* __restrict__ lA,
                               const float* __restrict__ lB,
                               const float* __restrict__ wscale) {
    int o  = blockIdx.x;
    int i4 = threadIdx.x;
    float b[RANK];
#pragma unroll
    for (int r = 0; r < RANK; r++) b[r] = lB[o * RANK + r];
    float inv = 1.0f / wscale[o];
    float4 w = reinterpret_cast<const float4*>(W + (size_t)o * IN_F)[i4];
    float m0 = w.x, m1 = w.y, m2 = w.z, m3 = w.w;
#pragma unroll
    for (int r = 0; r < RANK; r++) {
        float4 a = reinterpret_cast<const float4*>(lA + (size_t)r * IN_F)[i4];
        m0 += b[r] * a.x; m1 += b[r] * a.y; m2 += b[r] * a.z; m3 += b[r] * a.w;
    }
    reinterpret_cast<uint32_t*>(g_wq)[((size_t)o * IN_F) / 4 + i4] =
        pack4_e4m3(qclipf(m0 * inv), qclipf(m1 * inv),
                   qclipf(m2 * inv), qclipf(m3 * inv));
}

// ---------------------------------------------------------------------------
// Kernel 3: fp8 GEMM, 128x256x64 tiles, 3-stage cp.async, mma.sync m16n8k32.e4m3
// 512 threads = 16 warps in a 4(M) x 4(N) grid; warp tile 32x64.
// 64B rows, 4x16B chunks, XOR swizzle (identical byte geometry to round 3).
// ---------------------------------------------------------------------------
#define BM 128
#define BN 256
#define BK 64
#define KTILES (KDIM / BK)   // 64
#define ASTG 8192            // 128 rows x 64B
#define BSTG 16384           // 256 rows x 64B
#define STG  (ASTG + BSTG)   // 24576
#define STAGES 3
#define SMEM_TOTAL (STAGES * STG)   // 73728

__device__ __forceinline__ uint32_t swz(int row, int chunk) {
    return (uint32_t)(row * 64 + ((chunk ^ ((row >> 1) & 3)) << 4));
}

__device__ __forceinline__ void cp_async16(uint32_t saddr, const void* gaddr) {
    asm volatile("cp.async.cg.shared.global [%0], [%1], 16;\n"
                 :: "r"(saddr), "l"(gaddr));
}

__global__ __launch_bounds__(512) void gemm_kernel(
    float* __restrict__ out,
    const float* __restrict__ wscale,
    const float* __restrict__ bias,
    const float* __restrict__ tscales,
    const int*  __restrict__ step)
{
    extern __shared__ __align__(128) unsigned char smem[];
    const int tid   = threadIdx.x;
    const int lane  = tid & 31;
    const int warp  = tid >> 5;
    const int warpM = warp & 3;      // 0..3
    const int warpN = warp >> 2;     // 0..3
    const int bm0 = blockIdx.y * BM;
    const int bn0 = blockIdx.x * BN;

    const uint32_t sbase = (uint32_t)__cvta_generic_to_shared(smem);

    float acc[2][8][4];
#pragma unroll
    for (int mi = 0; mi < 2; mi++)
#pragma unroll
        for (int ni = 0; ni < 8; ni++)
#pragma unroll
            for (int c = 0; c < 4; c++) acc[mi][ni][c] = 0.0f;

    // ------- stage loader: A = 512 chunks (1/thread), B = 1024 (2/thread) ----
    auto load_tile = [&](int s, int kt) {
        const int k0 = kt * BK;
        const uint32_t abase = sbase + s * STG;
        const uint32_t bbase = abase + ASTG;
        {
            int r = tid >> 2, c = tid & 3;
            cp_async16(abase + swz(r, c), &g_xq[(size_t)(bm0 + r) * KDIM + k0 + c * 16]);
        }
#pragma unroll
        for (int p = 0; p < 2; p++) {
            int ci = tid + p * 512;
            int r = ci >> 2, c = ci & 3;
            cp_async16(bbase + swz(r, c), &g_wq[(size_t)(bn0 + r) * KDIM + k0 + c * 16]);
        }
        asm volatile("cp.async.commit_group;\n" ::);
    };

    load_tile(0, 0);
    load_tile(1, 1);

    const int q = lane >> 3;
    const int w = lane & 7;

#pragma unroll 1
    for (int kt = 0; kt < KTILES; ++kt) {
        const int s = kt % STAGES;
        if (kt + 2 < KTILES) {
            asm volatile("cp.async.wait_group 1;\n" ::);
        } else {
            asm volatile("cp.async.wait_group 0;\n" ::);
        }
        __syncthreads();
        if (kt + 2 < KTILES) load_tile((kt + 2) % STAGES, kt + 2);

        const uint32_t abase = sbase + s * STG;
        const uint32_t bbase = abase + ASTG;
#pragma unroll
        for (int kk = 0; kk < 2; kk++) {   // each kk = 32 fp8 along K
            uint32_t aF[2][4];
#pragma unroll
            for (int mi = 0; mi < 2; mi++) {
                int r  = warpM * 32 + mi * 16 + w + 8 * (q & 1);
                int ch = 2 * kk + (q >> 1);
                uint32_t addr = abase + swz(r, ch);
                asm volatile(
                    "ldmatrix.sync.aligned.m8n8.x4.shared.b16 {%0,%1,%2,%3}, [%4];\n"
                    : "=r"(aF[mi][0]), "=r"(aF[mi][1]), "=r"(aF[mi][2]), "=r"(aF[mi][3])
                    : "r"(addr));
            }
            uint32_t bF[8][2];
#pragma unroll
            for (int j = 0; j < 4; j++) {
                int r  = warpN * 64 + j * 16 + w + 8 * (q & 1);
                int ch = 2 * kk + (q >> 1);
                uint32_t addr = bbase + swz(r, ch);
                uint32_t t0, t1, t2, t3;
                asm volatile(
                    "ldmatrix.sync.aligned.m8n8.x4.shared.b16 {%0,%1,%2,%3}, [%4];\n"
                    : "=r"(t0), "=r"(t1), "=r"(t2), "=r"(t3)
                    : "r"(addr));
                bF[2 * j][0] = t0; bF[2 * j + 1][0] = t1;
                bF[2 * j][1] = t2; bF[2 * j + 1][1] = t3;
            }
#pragma unroll
            for (int mi = 0; mi < 2; mi++)
#pragma unroll
                for (int ni = 0; ni < 8; ni++) {
                    asm volatile(
                        "mma.sync.aligned.m16n8k32.row.col.f32.e4m3.e4m3.f32 "
                        "{%0,%1,%2,%3}, {%4,%5,%6,%7}, {%8,%9}, {%0,%1,%2,%3};\n"
                        : "+f"(acc[mi][ni][0]), "+f"(acc[mi][ni][1]),
                          "+f"(acc[mi][ni][2]), "+f"(acc[mi][ni][3])
                        : "r"(aF[mi][0]), "r"(aF[mi][1]), "r"(aF[mi][2]), "r"(aF[mi][3]),
                          "r"(bF[ni][0]), "r"(bF[ni][1]));
                }
        }
    }

    // ------- epilogue: out = acc * ts*scale[o] + bias[o] -------
    const float ts = tscales[*step];
#pragma unroll
    for (int ni = 0; ni < 8; ni++) {
        int gn = bn0 + warpN * 64 + ni * 8 + (lane & 3) * 2;
        float s0 = wscale[gn]     * ts;
        float s1 = wscale[gn + 1] * ts;
        float b0 = bias[gn];
        float b1 = bias[gn + 1];
#pragma unroll
        for (int mi = 0; mi < 2; mi++) {
            int gm = bm0 + warpM * 32 + mi * 16 + (lane >> 2);
            float2 r01;
            r01.x = acc[mi][ni][0] * s0 + b0;
            r01.y = acc[mi][ni][1] * s1 + b1;
            *reinterpret_cast<float2*>(&out[(size_t)gm * NDIM + gn]) = r01;
            float2 r23;
            r23.x = acc[mi][ni][2] * s0 + b0;
            r23.y = acc[mi][ni][3] * s1 + b1;
            *reinterpret_cast<float2*>(&out[(size_t)(gm + 8) * NDIM + gn]) = r23;
        }
    }
}

// ---------------------------------------------------------------------------
// launch: 0=x 1=W 2=lora_A 3=lora_B 4=weight_scale 5=temporal_scales 6=bias 7=step
// ---------------------------------------------------------------------------
extern "C" void kernel_launch(void* const* d_in, const int* in_sizes, int n_in,
                              void* d_out, int out_size) {
    const float* x   = (const float*)d_in[0];
    const float* W   = (const float*)d_in[1];
    const float* lA  = (const float*)d_in[2];
    const float* lB  = (const float*)d_in[3];
    const float* ws  = (const float*)d_in[4];
    const float* tsc = (const float*)d_in[5];
    const float* bia = (const float*)d_in[6];
    const int*   stp = (const int*)  d_in[7];
    float* out = (float*)d_out;

    {
        int n4 = (MTOT * KDIM) / 4;
        quant_x_kernel<<<(n4 + 255) / 256, 256>>>(x, tsc, stp);
    }
    quant_w_kernel<<<NDIM, 1024>>>(W, lA, lB, ws);
    {
        static int smem_set = 0;
        if (!smem_set) {
            cudaFuncSetAttribute(gemm_kernel,
                                 cudaFuncAttributeMaxDynamicSharedMemorySize,
                                 SMEM_TOTAL);
            smem_set = 1;
        }
        dim3 grid(NDIM / BN, MTOT / BM);   // (16, 64)
        gemm_kernel<<<grid, 512, SMEM_TOTAL>>>(out, ws, bia, tsc, stp);
    }
}

// round 5
// speedup vs baseline: 2.4103x; 1.0618x over previous
#include <cuda_runtime.h>
#include <cuda_bf16.h>
#include <cuda_fp8.h>
#include <cstdint>

// Problem constants
#define IN_F   4096
#define OUT_F  4096
#define RANK   8
#define MTOT   8192
#define KDIM   4096
#define NDIM   4096

// Quantized operand scratch: integer codes in [-8,7] stored as e4m3 (exact)
__device__ uint8_t g_xq[(size_t)MTOT * KDIM];   // 32 MB
__device__ uint8_t g_wq[(size_t)NDIM * KDIM];   // 16 MB

__device__ __forceinline__ float qclipf(float v) {
    return fminf(7.0f, fmaxf(-8.0f, rintf(v)));
}
__device__ __forceinline__ uint32_t pack4_e4m3(float a, float b, float c, float d) {
    uint32_t r0 = __nv_cvt_float_to_fp8(a, __NV_SATFINITE, __NV_E4M3);
    uint32_t r1 = __nv_cvt_float_to_fp8(b, __NV_SATFINITE, __NV_E4M3);
    uint32_t r2 = __nv_cvt_float_to_fp8(c, __NV_SATFINITE, __NV_E4M3);
    uint32_t r3 = __nv_cvt_float_to_fp8(d, __NV_SATFINITE, __NV_E4M3);
    return r0 | (r1 << 8) | (r2 << 16) | (r3 << 24);
}

// ---------------------------------------------------------------------------
// Kernel 1: activation quantization -> packed e4m3
// ---------------------------------------------------------------------------
__global__ void quant_x_kernel(const float* __restrict__ x,
                               const float* __restrict__ tscales,
                               const int*   __restrict__ step) {
    int i = blockIdx.x * blockDim.x + threadIdx.x;
    const int n4 = (MTOT * KDIM) / 4;
    if (i >= n4) return;
    float inv = 1.0f / tscales[*step];
    float4 v = reinterpret_cast<const float4*>(x)[i];
    reinterpret_cast<uint32_t*>(g_xq)[i] =
        pack4_e4m3(qclipf(v.x * inv), qclipf(v.y * inv),
                   qclipf(v.z * inv), qclipf(v.w * inv));
}

// ---------------------------------------------------------------------------
// Kernel 2: LoRA merge + weight quantization -> packed e4m3
// ---------------------------------------------------------------------------
__global__ void quant_w_kernel(const float* __restrict__ W,
                               const float* __restrict__ lA,
                               const float* __restrict__ lB,
                               const float* __restrict__ wscale) {
    int o  = blockIdx.x;
    int i4 = threadIdx.x;
    float b[RANK];
#pragma unroll
    for (int r = 0; r < RANK; r++) b[r] = lB[o * RANK + r];
    float inv = 1.0f / wscale[o];
    float4 w = reinterpret_cast<const float4*>(W + (size_t)o * IN_F)[i4];
    float m0 = w.x, m1 = w.y, m2 = w.z, m3 = w.w;
#pragma unroll
    for (int r = 0; r < RANK; r++) {
        float4 a = reinterpret_cast<const float4*>(lA + (size_t)r * IN_F)[i4];
        m0 += b[r] * a.x; m1 += b[r] * a.y; m2 += b[r] * a.z; m3 += b[r] * a.w;
    }
    reinterpret_cast<uint32_t*>(g_wq)[((size_t)o * IN_F) / 4 + i4] =
        pack4_e4m3(qclipf(m0 * inv), qclipf(m1 * inv),
                   qclipf(m2 * inv), qclipf(m3 * inv));
}

// ---------------------------------------------------------------------------
// Kernel 3: fp8 GEMM, max-ILP variant.
// CTA tile 128x256x64, 256 threads = 8 warps in 2(M) x 4(N); warp tile 64x64.
// 32 independent accumulator chains per warp; all fragments for BK=64 loaded
// up-front (16 ldmatrix.x4), then 64 mma. 3-stage cp.async, 1 barrier per kt.
// ---------------------------------------------------------------------------
#define BM 128
#define BN 256
#define BK 64
#define KTILES (KDIM / BK)   // 64
#define ASTG 8192            // 128 rows x 64B
#define BSTG 16384           // 256 rows x 64B
#define STG  (ASTG + BSTG)   // 24576
#define STAGES 3
#define SMEM_TOTAL (STAGES * STG)   // 73728

__device__ __forceinline__ uint32_t swz(int row, int chunk) {
    return (uint32_t)(row * 64 + ((chunk ^ ((row >> 1) & 3)) << 4));
}

__device__ __forceinline__ void cp_async16(uint32_t saddr, const void* gaddr) {
    asm volatile("cp.async.cg.shared.global [%0], [%1], 16;\n"
                 :: "r"(saddr), "l"(gaddr));
}

__global__ __launch_bounds__(256, 1) void gemm_kernel(
    float* __restrict__ out,
    const float* __restrict__ wscale,
    const float* __restrict__ bias,
    const float* __restrict__ tscales,
    const int*  __restrict__ step)
{
    extern __shared__ __align__(128) unsigned char smem[];
    const int tid   = threadIdx.x;
    const int lane  = tid & 31;
    const int warp  = tid >> 5;
    const int warpM = warp >> 2;     // 0..1
    const int warpN = warp & 3;      // 0..3
    const int bm0 = blockIdx.y * BM;
    const int bn0 = blockIdx.x * BN;

    const uint32_t sbase = (uint32_t)__cvta_generic_to_shared(smem);

    float acc[4][8][4];
#pragma unroll
    for (int mi = 0; mi < 4; mi++)
#pragma unroll
        for (int ni = 0; ni < 8; ni++)
#pragma unroll
            for (int c = 0; c < 4; c++) acc[mi][ni][c] = 0.0f;

    // stage loader: A = 512 chunks (2/thread), B = 1024 chunks (4/thread)
    auto load_tile = [&](int s, int kt) {
        const int k0 = kt * BK;
        const uint32_t abase = sbase + s * STG;
        const uint32_t bbase = abase + ASTG;
#pragma unroll
        for (int p = 0; p < 2; p++) {
            int ci = tid + p * 256;
            int r = ci >> 2, c = ci & 3;
            cp_async16(abase + swz(r, c), &g_xq[(size_t)(bm0 + r) * KDIM + k0 + c * 16]);
        }
#pragma unroll
        for (int p = 0; p < 4; p++) {
            int ci = tid + p * 256;
            int r = ci >> 2, c = ci & 3;
            cp_async16(bbase + swz(r, c), &g_wq[(size_t)(bn0 + r) * KDIM + k0 + c * 16]);
        }
        asm volatile("cp.async.commit_group;\n" ::);
    };

    load_tile(0, 0);
    load_tile(1, 1);

    const int q = lane >> 3;
    const int w = lane & 7;

#pragma unroll 1
    for (int kt = 0; kt < KTILES; ++kt) {
        const int s = kt % STAGES;
        if (kt + 2 < KTILES) {
            asm volatile("cp.async.wait_group 1;\n" ::);
        } else {
            asm volatile("cp.async.wait_group 0;\n" ::);
        }
        __syncthreads();
        if (kt + 2 < KTILES) load_tile((kt + 2) % STAGES, kt + 2);

        const uint32_t abase = sbase + s * STG;
        const uint32_t bbase = abase + ASTG;

        // ---- load ALL fragments for this K-tile (both kk halves) ----
        uint32_t aF[2][4][4];
        uint32_t bF[2][8][2];
#pragma unroll
        for (int kk = 0; kk < 2; kk++) {
            const int ch = 2 * kk + (q >> 1);
#pragma unroll
            for (int mi = 0; mi < 4; mi++) {
                int r = warpM * 64 + mi * 16 + w + 8 * (q & 1);
                uint32_t addr = abase + swz(r, ch);
                asm volatile(
                    "ldmatrix.sync.aligned.m8n8.x4.shared.b16 {%0,%1,%2,%3}, [%4];\n"
                    : "=r"(aF[kk][mi][0]), "=r"(aF[kk][mi][1]),
                      "=r"(aF[kk][mi][2]), "=r"(aF[kk][mi][3])
                    : "r"(addr));
            }
#pragma unroll
            for (int j = 0; j < 4; j++) {
                int r = warpN * 64 + j * 16 + w + 8 * (q & 1);
                uint32_t addr = bbase + swz(r, ch);
                uint32_t t0, t1, t2, t3;
                asm volatile(
                    "ldmatrix.sync.aligned.m8n8.x4.shared.b16 {%0,%1,%2,%3}, [%4];\n"
                    : "=r"(t0), "=r"(t1), "=r"(t2), "=r"(t3)
                    : "r"(addr));
                bF[kk][2 * j][0] = t0; bF[kk][2 * j + 1][0] = t1;
                bF[kk][2 * j][1] = t2; bF[kk][2 * j + 1][1] = t3;
            }
        }
        // ---- 64 mma, 32 independent chains ----
#pragma unroll
        for (int kk = 0; kk < 2; kk++)
#pragma unroll
            for (int mi = 0; mi < 4; mi++)
#pragma unroll
                for (int ni = 0; ni < 8; ni++) {
                    asm volatile(
                        "mma.sync.aligned.m16n8k32.row.col.f32.e4m3.e4m3.f32 "
                        "{%0,%1,%2,%3}, {%4,%5,%6,%7}, {%8,%9}, {%0,%1,%2,%3};\n"
                        : "+f"(acc[mi][ni][0]), "+f"(acc[mi][ni][1]),
                          "+f"(acc[mi][ni][2]), "+f"(acc[mi][ni][3])
                        : "r"(aF[kk][mi][0]), "r"(aF[kk][mi][1]),
                          "r"(aF[kk][mi][2]), "r"(aF[kk][mi][3]),
                          "r"(bF[kk][ni][0]), "r"(bF[kk][ni][1]));
                }
    }

    // ------- epilogue: out = acc * ts*scale[o] + bias[o] -------
    const float ts = tscales[*step];
#pragma unroll
    for (int ni = 0; ni < 8; ni++) {
        int gn = bn0 + warpN * 64 + ni * 8 + (lane & 3) * 2;
        float s0 = wscale[gn]     * ts;
        float s1 = wscale[gn + 1] * ts;
        float b0 = bias[gn];
        float b1 = bias[gn + 1];
#pragma unroll
        for (int mi = 0; mi < 4; mi++) {
            int gm = bm0 + warpM * 64 + mi * 16 + (lane >> 2);
            float2 r01;
            r01.x = acc[mi][ni][0] * s0 + b0;
            r01.y = acc[mi][ni][1] * s1 + b1;
            *reinterpret_cast<float2*>(&out[(size_t)gm * NDIM + gn]) = r01;
            float2 r23;
            r23.x = acc[mi][ni][2] * s0 + b0;
            r23.y = acc[mi][ni][3] * s1 + b1;
            *reinterpret_cast<float2*>(&out[(size_t)(gm + 8) * NDIM + gn]) = r23;
        }
    }
}

// ---------------------------------------------------------------------------
// launch: 0=x 1=W 2=lora_A 3=lora_B 4=weight_scale 5=temporal_scales 6=bias 7=step
// ---------------------------------------------------------------------------
extern "C" void kernel_launch(void* const* d_in, const int* in_sizes, int n_in,
                              void* d_out, int out_size) {
    const float* x   = (const float*)d_in[0];
    const float* W   = (const float*)d_in[1];
    const float* lA  = (const float*)d_in[2];
    const float* lB  = (const float*)d_in[3];
    const float* ws  = (const float*)d_in[4];
    const float* tsc = (const float*)d_in[5];
    const float* bia = (const float*)d_in[6];
    const int*   stp = (const int*)  d_in[7];
    float* out = (float*)d_out;

    {
        int n4 = (MTOT * KDIM) / 4;
        quant_x_kernel<<<(n4 + 255) / 256, 256>>>(x, tsc, stp);
    }
    quant_w_kernel<<<NDIM, 1024>>>(W, lA, lB, ws);
    {
        static int smem_set = 0;
        if (!smem_set) {
            cudaFuncSetAttribute(gemm_kernel,
                                 cudaFuncAttributeMaxDynamicSharedMemorySize,
                                 SMEM_TOTAL);
            smem_set = 1;
        }
        dim3 grid(NDIM / BN, MTOT / BM);   // (16, 64)
        gemm_kernel<<<grid, 256, SMEM_TOTAL>>>(out, ws, bia, tsc, stp);
    }
}

// round 6
// speedup vs baseline: 2.6381x; 1.0945x over previous
#include <cuda_runtime.h>
#include <cuda_bf16.h>
#include <cuda_fp8.h>
#include <cstdint>

// Problem constants
#define IN_F   4096
#define OUT_F  4096
#define RANK   8
#define MTOT   8192
#define KDIM   4096
#define NDIM   4096

// Quantized operand scratch: integer codes in [-8,7] stored as e4m3 (exact)
__device__ uint8_t g_xq[(size_t)MTOT * KDIM];   // 32 MB
__device__ uint8_t g_wq[(size_t)NDIM * KDIM];   // 16 MB

__device__ __forceinline__ float qclipf(float v) {
    return fminf(7.0f, fmaxf(-8.0f, rintf(v)));
}
__device__ __forceinline__ uint32_t pack4_e4m3(float a, float b, float c, float d) {
    uint32_t r0 = __nv_cvt_float_to_fp8(a, __NV_SATFINITE, __NV_E4M3);
    uint32_t r1 = __nv_cvt_float_to_fp8(b, __NV_SATFINITE, __NV_E4M3);
    uint32_t r2 = __nv_cvt_float_to_fp8(c, __NV_SATFINITE, __NV_E4M3);
    uint32_t r3 = __nv_cvt_float_to_fp8(d, __NV_SATFINITE, __NV_E4M3);
    return r0 | (r1 << 8) | (r2 << 16) | (r3 << 24);
}

// ---------------------------------------------------------------------------
// Kernel 1: activation quantization -> packed e4m3.  4 float4 per thread
// (front-batched, MLP=4), one 16B store.
// ---------------------------------------------------------------------------
__global__ void quant_x_kernel(const float* __restrict__ x,
                               const float* __restrict__ tscales,
                               const int*   __restrict__ step) {
    int t = blockIdx.x * blockDim.x + threadIdx.x;   // 16-element group index
    const int ngrp = (MTOT * KDIM) / 16;
    if (t >= ngrp) return;
    float inv = 1.0f / tscales[*step];
    const float4* src = reinterpret_cast<const float4*>(x) + (size_t)t * 4;
    float4 v0 = src[0];
    float4 v1 = src[1];
    float4 v2 = src[2];
    float4 v3 = src[3];
    uint4 o;
    o.x = pack4_e4m3(qclipf(v0.x * inv), qclipf(v0.y * inv),
                     qclipf(v0.z * inv), qclipf(v0.w * inv));
    o.y = pack4_e4m3(qclipf(v1.x * inv), qclipf(v1.y * inv),
                     qclipf(v1.z * inv), qclipf(v1.w * inv));
    o.z = pack4_e4m3(qclipf(v2.x * inv), qclipf(v2.y * inv),
                     qclipf(v2.z * inv), qclipf(v2.w * inv));
    o.w = pack4_e4m3(qclipf(v3.x * inv), qclipf(v3.y * inv),
                     qclipf(v3.z * inv), qclipf(v3.w * inv));
    reinterpret_cast<uint4*>(g_xq)[t] = o;
}

// ---------------------------------------------------------------------------
// Kernel 2: LoRA merge + weight quantization -> packed e4m3
// ---------------------------------------------------------------------------
__global__ void quant_w_kernel(const float* __restrict__ W,
                               const float* __restrict__ lA,
                               const float* __restrict__ lB,
                               const float* __restrict__ wscale) {
    int o  = blockIdx.x;
    int i4 = threadIdx.x;
    float b[RANK];
#pragma unroll
    for (int r = 0; r < RANK; r++) b[r] = lB[o * RANK + r];
    float inv = 1.0f / wscale[o];
    float4 w = reinterpret_cast<const float4*>(W + (size_t)o * IN_F)[i4];
    float m0 = w.x, m1 = w.y, m2 = w.z, m3 = w.w;
#pragma unroll
    for (int r = 0; r < RANK; r++) {
        float4 a = reinterpret_cast<const float4*>(lA + (size_t)r * IN_F)[i4];
        m0 += b[r] * a.x; m1 += b[r] * a.y; m2 += b[r] * a.z; m3 += b[r] * a.w;
    }
    reinterpret_cast<uint32_t*>(g_wq)[((size_t)o * IN_F) / 4 + i4] =
        pack4_e4m3(qclipf(m0 * inv), qclipf(m1 * inv),
                   qclipf(m2 * inv), qclipf(m3 * inv));
}

// ---------------------------------------------------------------------------
// Kernel 3: fp8 GEMM.
// CTA tile 128x256x128, 256 threads = 8 warps (2M x 4N), warp tile 64x64.
// Rows are 128B (full SW128 swizzle). 3-stage cp.async, one barrier per
// K-tile (32 total). Fragments register-double-buffered across the 4 kk
// sub-steps: load kk+1 while mma kk.
// ---------------------------------------------------------------------------
#define BM 128
#define BN 256
#define BK 128
#define KTILES (KDIM / BK)   // 32
#define ASTG (BM * 128)      // 16384
#define BSTG (BN * 128)      // 32768
#define STG  (ASTG + BSTG)   // 49152
#define STAGES 3
#define SMEM_TOTAL (STAGES * STG)   // 147456

__device__ __forceinline__ uint32_t swz128(int row, int chunk) {
    return (uint32_t)(row * 128 + ((chunk ^ (row & 7)) << 4));
}

__device__ __forceinline__ void cp_async16(uint32_t saddr, const void* gaddr) {
    asm volatile("cp.async.cg.shared.global [%0], [%1], 16;\n"
                 :: "r"(saddr), "l"(gaddr));
}

__device__ __forceinline__ void ldm_x4(uint32_t* d, uint32_t addr) {
    asm volatile("ldmatrix.sync.aligned.m8n8.x4.shared.b16 {%0,%1,%2,%3}, [%4];\n"
                 : "=r"(d[0]), "=r"(d[1]), "=r"(d[2]), "=r"(d[3]) : "r"(addr));
}

__global__ __launch_bounds__(256, 1) void gemm_kernel(
    float* __restrict__ out,
    const float* __restrict__ wscale,
    const float* __restrict__ bias,
    const float* __restrict__ tscales,
    const int*  __restrict__ step)
{
    extern __shared__ __align__(128) unsigned char smem[];
    const int tid   = threadIdx.x;
    const int lane  = tid & 31;
    const int warp  = tid >> 5;
    const int warpM = warp >> 2;     // 0..1
    const int warpN = warp & 3;      // 0..3
    const int bm0 = blockIdx.y * BM;
    const int bn0 = blockIdx.x * BN;

    const uint32_t sbase = (uint32_t)__cvta_generic_to_shared(smem);

    float acc[4][8][4];
#pragma unroll
    for (int mi = 0; mi < 4; mi++)
#pragma unroll
        for (int ni = 0; ni < 8; ni++)
#pragma unroll
            for (int c = 0; c < 4; c++) acc[mi][ni][c] = 0.0f;

    // stage loader: A = 1024 chunks (4/thread), B = 2048 chunks (8/thread)
    auto load_tile = [&](int s, int kt) {
        const int k0 = kt * BK;
        const uint32_t abase = sbase + s * STG;
        const uint32_t bbase = abase + ASTG;
#pragma unroll
        for (int p = 0; p < 4; p++) {
            int ci = tid + p * 256;       // 0..1023
            int r = ci >> 3, c = ci & 7;
            cp_async16(abase + swz128(r, c),
                       &g_xq[(size_t)(bm0 + r) * KDIM + k0 + c * 16]);
        }
#pragma unroll
        for (int p = 0; p < 8; p++) {
            int ci = tid + p * 256;       // 0..2047
            int r = ci >> 3, c = ci & 7;
            cp_async16(bbase + swz128(r, c),
                       &g_wq[(size_t)(bn0 + r) * KDIM + k0 + c * 16]);
        }
        asm volatile("cp.async.commit_group;\n" ::);
    };

    load_tile(0, 0);
    load_tile(1, 1);

    const int q = lane >> 3;
    const int w = lane & 7;
    const int arow = warpM * 64 + w + 8 * (q & 1);   // + mi*16
    const int brow = warpN * 64 + w + 8 * (q & 1);   // + j*16

    uint32_t aF[2][4][4];
    uint32_t bF[2][8][2];

    // fragment loader for one kk sub-step into buffer buf
    auto load_frags = [&](uint32_t abase, uint32_t bbase, int kk, int buf) {
        const int ch = 2 * kk + (q >> 1);
#pragma unroll
        for (int mi = 0; mi < 4; mi++)
            ldm_x4(aF[buf][mi], abase + swz128(arow + mi * 16, ch));
#pragma unroll
        for (int j = 0; j < 4; j++) {
            uint32_t t[4];
            ldm_x4(t, bbase + swz128(brow + j * 16, ch));
            bF[buf][2 * j][0] = t[0]; bF[buf][2 * j + 1][0] = t[1];
            bF[buf][2 * j][1] = t[2]; bF[buf][2 * j + 1][1] = t[3];
        }
    };

    auto do_mma = [&](int buf) {
#pragma unroll
        for (int mi = 0; mi < 4; mi++)
#pragma unroll
            for (int ni = 0; ni < 8; ni++) {
                asm volatile(
                    "mma.sync.aligned.m16n8k32.row.col.f32.e4m3.e4m3.f32 "
                    "{%0,%1,%2,%3}, {%4,%5,%6,%7}, {%8,%9}, {%0,%1,%2,%3};\n"
                    : "+f"(acc[mi][ni][0]), "+f"(acc[mi][ni][1]),
                      "+f"(acc[mi][ni][2]), "+f"(acc[mi][ni][3])
                    : "r"(aF[buf][mi][0]), "r"(aF[buf][mi][1]),
                      "r"(aF[buf][mi][2]), "r"(aF[buf][mi][3]),
                      "r"(bF[buf][ni][0]), "r"(bF[buf][ni][1]));
            }
    };

#pragma unroll 1
    for (int kt = 0; kt < KTILES; ++kt) {
        const int s = kt % STAGES;
        if (kt + 2 < KTILES) {
            asm volatile("cp.async.wait_group 1;\n" ::);
        } else {
            asm volatile("cp.async.wait_group 0;\n" ::);
        }
        __syncthreads();
        if (kt + 2 < KTILES) load_tile((kt + 2) % STAGES, kt + 2);

        const uint32_t abase = sbase + s * STG;
        const uint32_t bbase = abase + ASTG;

        load_frags(abase, bbase, 0, 0);
#pragma unroll
        for (int kk = 0; kk < 4; kk++) {
            const int cur = kk & 1;
            if (kk < 3) load_frags(abase, bbase, kk + 1, cur ^ 1);
            do_mma(cur);
        }
    }

    // ------- epilogue: out = acc * ts*scale[o] + bias[o] -------
    const float ts = tscales[*step];
#pragma unroll
    for (int ni = 0; ni < 8; ni++) {
        int gn = bn0 + warpN * 64 + ni * 8 + (lane & 3) * 2;
        float s0 = wscale[gn]     * ts;
        float s1 = wscale[gn + 1] * ts;
        float b0 = bias[gn];
        float b1 = bias[gn + 1];
#pragma unroll
        for (int mi = 0; mi < 4; mi++) {
            int gm = bm0 + warpM * 64 + mi * 16 + (lane >> 2);
            float2 r01;
            r01.x = acc[mi][ni][0] * s0 + b0;
            r01.y = acc[mi][ni][1] * s1 + b1;
            *reinterpret_cast<float2*>(&out[(size_t)gm * NDIM + gn]) = r01;
            float2 r23;
            r23.x = acc[mi][ni][2] * s0 + b0;
            r23.y = acc[mi][ni][3] * s1 + b1;
            *reinterpret_cast<float2*>(&out[(size_t)(gm + 8) * NDIM + gn]) = r23;
        }
    }
}

// ---------------------------------------------------------------------------
// launch: 0=x 1=W 2=lora_A 3=lora_B 4=weight_scale 5=temporal_scales 6=bias 7=step
// ---------------------------------------------------------------------------
extern "C" void kernel_launch(void* const* d_in, const int* in_sizes, int n_in,
                              void* d_out, int out_size) {
    const float* x   = (const float*)d_in[0];
    const float* W   = (const float*)d_in[1];
    const float* lA  = (const float*)d_in[2];
    const float* lB  = (const float*)d_in[3];
    const float* ws  = (const float*)d_in[4];
    const float* tsc = (const float*)d_in[5];
    const float* bia = (const float*)d_in[6];
    const int*   stp = (const int*)  d_in[7];
    float* out = (float*)d_out;

    {
        int ngrp = (MTOT * KDIM) / 16;   // 2M threads
        quant_x_kernel<<<(ngrp + 255) / 256, 256>>>(x, tsc, stp);
    }
    quant_w_kernel<<<NDIM, 1024>>>(W, lA, lB, ws);
    {
        static int smem_set = 0;
        if (!smem_set) {
            cudaFuncSetAttribute(gemm_kernel,
                                 cudaFuncAttributeMaxDynamicSharedMemorySize,
                                 SMEM_TOTAL);
            smem_set = 1;
        }
        dim3 grid(NDIM / BN, MTOT / BM);   // (16, 64)
        gemm_kernel<<<grid, 256, SMEM_TOTAL>>>(out, ws, bia, tsc, stp);
    }
}